// round 1
// baseline (speedup 1.0000x reference)
#include <cuda_runtime.h>
#include <cuda_bf16.h>
#include <cstdint>

// Problem constants (fixed by the dataset)
#define NE 50000
#define NR 2000
#define EMAX 800000
#define NHEAD 8
#define DIM 128
#define NEG_SLOPE 0.01f

// ---------------- scratch (static device globals; no allocation) -------------
__device__ float g_ph[NE * NHEAD];      // x_e @ Wh.T
__device__ float g_pt[NE * NHEAD];      // x_e @ Wt.T
__device__ float g_pr[NR * NHEAD];      // x_r @ Wr.T
__device__ int   g_deg[2 * NE];         // degrees: [0,NE)=h side, [NE,2NE)=t side
__device__ int   g_coffs[2 * NE + 1];   // exclusive offsets (combined h|t CSR)
__device__ int   g_cur[2 * NE];         // scatter cursors
__device__ int   g_elist[2 * EMAX];     // edge ids, grouped by (side,node)
__device__ int   g_rel32[EMAX];         // rel cast to int32
__device__ int   g_is64;                // 1 if edge_index/rel are int64

// ---------------- helpers ----------------------------------------------------
__device__ __forceinline__ int load_idx(const void* p, long i, int is64) {
    if (is64) return (int)((const long long*)p)[i];
    return ((const int*)p)[i];
}

// ---------------- kernel 0: zero degrees + detect index width ---------------
__global__ void k_zero_detect(const unsigned* ei_words) {
    int i = blockIdx.x * blockDim.x + threadIdx.x;
    if (i < 2 * NE) g_deg[i] = 0;
    if (blockIdx.x == 0 && threadIdx.x < 32) {
        // If int64: odd 32-bit words are the (zero) high halves of small values.
        unsigned w = ei_words[2 * threadIdx.x + 1];
        unsigned ball = __ballot_sync(0xffffffffu, w == 0u);
        if (threadIdx.x == 0) g_is64 = (ball == 0xffffffffu) ? 1 : 0;
    }
}

// ---------------- kernel 1: projections (warp per row) -----------------------
// mode 0: x=x_e, Wa=Wh -> g_ph, Wb=Wt -> g_pt
// mode 1: x=x_r, Wa=Wr -> g_pr
__global__ __launch_bounds__(256) void k_proj(const float* __restrict__ x,
                                              const float* __restrict__ Wa,
                                              const float* __restrict__ Wb,
                                              int n, int mode) {
    int w = (blockIdx.x * blockDim.x + threadIdx.x) >> 5;
    int lane = threadIdx.x & 31;
    if (w >= n) return;
    float* pa = (mode == 0) ? g_ph : g_pr;
    float* pb = (mode == 0) ? g_pt : nullptr;

    const float* xr = x + (long)w * DIM;
    float x0 = xr[lane], x1 = xr[lane + 32], x2 = xr[lane + 64], x3 = xr[lane + 96];

#pragma unroll
    for (int h = 0; h < NHEAD; h++) {
        const float* wa = Wa + h * DIM;
        float a = x0 * wa[lane] + x1 * wa[lane + 32] + x2 * wa[lane + 64] + x3 * wa[lane + 96];
#pragma unroll
        for (int off = 16; off > 0; off >>= 1) a += __shfl_xor_sync(0xffffffffu, a, off);
        if (lane == 0) pa[w * NHEAD + h] = a;
        if (pb) {
            const float* wb = Wb + h * DIM;
            float b = x0 * wb[lane] + x1 * wb[lane + 32] + x2 * wb[lane + 64] + x3 * wb[lane + 96];
#pragma unroll
            for (int off = 16; off > 0; off >>= 1) b += __shfl_xor_sync(0xffffffffu, b, off);
            if (lane == 0) pb[w * NHEAD + h] = b;
        }
    }
}

// ---------------- kernel 2: degree histogram + rel cast ----------------------
__global__ __launch_bounds__(256) void k_hist(const void* ei, const void* rel, int E) {
    int e = blockIdx.x * blockDim.x + threadIdx.x;
    if (e >= E) return;
    int is64 = g_is64;
    int h = load_idx(ei, e, is64);
    int t = load_idx(ei, (long)E + e, is64);
    atomicAdd(&g_deg[h], 1);
    atomicAdd(&g_deg[NE + t], 1);
    g_rel32[e] = load_idx(rel, e, is64);
}

// ---------------- kernel 3: exclusive scan over 2*NE degrees (1 block) -------
__global__ __launch_bounds__(1024) void k_scan(int E) {
    __shared__ int sh[1024];
    __shared__ int carry;
    int tid = threadIdx.x;
    if (tid == 0) carry = 0;
    __syncthreads();
    const int total = 2 * NE;
    for (int base = 0; base < total; base += 4096) {
        int idx = base + tid * 4;
        int v0 = 0, v1 = 0, v2 = 0, v3 = 0;
        if (idx + 0 < total) v0 = g_deg[idx + 0];
        if (idx + 1 < total) v1 = g_deg[idx + 1];
        if (idx + 2 < total) v2 = g_deg[idx + 2];
        if (idx + 3 < total) v3 = g_deg[idx + 3];
        int s = v0 + v1 + v2 + v3;
        sh[tid] = s;
        __syncthreads();
        for (int off = 1; off < 1024; off <<= 1) {
            int t_ = 0;
            if (tid >= off) t_ = sh[tid - off];
            __syncthreads();
            if (tid >= off) sh[tid] += t_;
            __syncthreads();
        }
        int excl = carry + sh[tid] - s;
        if (idx + 0 < total) { g_coffs[idx + 0] = excl; g_cur[idx + 0] = excl; excl += v0; }
        if (idx + 1 < total) { g_coffs[idx + 1] = excl; g_cur[idx + 1] = excl; excl += v1; }
        if (idx + 2 < total) { g_coffs[idx + 2] = excl; g_cur[idx + 2] = excl; excl += v2; }
        if (idx + 3 < total) { g_coffs[idx + 3] = excl; g_cur[idx + 3] = excl; }
        __syncthreads();
        if (tid == 0) carry = carry + sh[1023];
        __syncthreads();
    }
    if (tid == 0) g_coffs[total] = 2 * E;
}

// ---------------- kernel 4: scatter edges into CSR ----------------------------
__global__ __launch_bounds__(256) void k_fill(const void* ei, int E) {
    int e = blockIdx.x * blockDim.x + threadIdx.x;
    if (e >= E) return;
    int is64 = g_is64;
    int h = load_idx(ei, e, is64);
    int t = load_idx(ei, (long)E + e, is64);
    int p1 = atomicAdd(&g_cur[h], 1);
    g_elist[p1] = e;
    int p2 = atomicAdd(&g_cur[NE + t], 1);
    g_elist[p2] = e;
}

// ---------------- kernel 5: softmax denominators + aggregation ---------------
// One warp per (side, node). Task gw in [0, 2*NE): gw<NE => h side, else t side.
__global__ __launch_bounds__(256) void k_agg(const float* __restrict__ x_r,
                                             float* __restrict__ out) {
    int gw = (blockIdx.x * blockDim.x + threadIdx.x) >> 5;
    int lane = threadIdx.x & 31;
    if (gw >= 2 * NE) return;
    int side = (gw < NE) ? 0 : 1;
    int node = (gw < NE) ? gw : gw - NE;
    const float* p = side ? g_pt : g_ph;

    int start = g_coffs[gw];
    int end = g_coffs[gw + 1];

    // per-node head scores (broadcast L1 loads)
    float pn[NHEAD];
#pragma unroll
    for (int h = 0; h < NHEAD; h++) pn[h] = p[node * NHEAD + h];

    // ---- phase 1: denominators per head (no max subtraction: scores ~N(0,2))
    float exs[NHEAD];
#pragma unroll
    for (int h = 0; h < NHEAD; h++) exs[h] = 0.0f;
    for (int j = start + lane; j < end; j += 32) {
        int e = g_elist[j];
        int r = g_rel32[e];
        const float* pr = g_pr + r * NHEAD;
#pragma unroll
        for (int h = 0; h < NHEAD; h++) {
            float s = pn[h] + pr[h];
            s = (s > 0.0f) ? s : NEG_SLOPE * s;
            exs[h] += __expf(s);
        }
    }
#pragma unroll
    for (int h = 0; h < NHEAD; h++) {
        float v = exs[h];
#pragma unroll
        for (int off = 16; off > 0; off >>= 1) v += __shfl_xor_sync(0xffffffffu, v, off);
        exs[h] = v;  // denom_h on all lanes
    }

    // this lane's head (lane&7); avoid dynamic register-array indexing
    int myh = lane & 7;
    float pn_my = 0.0f, den_my = 0.0f;
#pragma unroll
    for (int h = 0; h < NHEAD; h++) {
        pn_my = (myh == h) ? pn[h] : pn_my;
        den_my = (myh == h) ? exs[h] : den_my;
    }
    float invd_my = 1.0f / (den_my + 1e-16f);

    // ---- phase 2: serial over edges, whole warp cooperates per edge
    float acc0 = 0.0f, acc1 = 0.0f, acc2 = 0.0f, acc3 = 0.0f;
    for (int j = start; j < end; j++) {
        int e = g_elist[j];      // uniform address -> broadcast
        int r = g_rel32[e];
        float s = pn_my + g_pr[r * NHEAD + myh];
        s = (s > 0.0f) ? s : NEG_SLOPE * s;
        float ex = __expf(s) * invd_my;
        // sum over the 8 heads within each 8-lane group (groups are identical)
        ex += __shfl_xor_sync(0xffffffffu, ex, 1);
        ex += __shfl_xor_sync(0xffffffffu, ex, 2);
        ex += __shfl_xor_sync(0xffffffffu, ex, 4);
        float a = ex * 0.125f;   // mean over heads; same on all lanes
        const float* xr = x_r + (long)r * DIM;
        acc0 += a * xr[lane];
        acc1 += a * xr[lane + 32];
        acc2 += a * xr[lane + 64];
        acc3 += a * xr[lane + 96];
    }

    float* ob = out + (long)node * (2 * DIM) + side * DIM;
    ob[lane] = acc0;
    ob[lane + 32] = acc1;
    ob[lane + 64] = acc2;
    ob[lane + 96] = acc3;
}

// ---------------- launch ------------------------------------------------------
extern "C" void kernel_launch(void* const* d_in, const int* in_sizes, int n_in,
                              void* d_out, int out_size) {
    const float* x_e = (const float*)d_in[0];
    const float* x_r = (const float*)d_in[1];
    const float* Wh  = (const float*)d_in[2];
    const float* Wt  = (const float*)d_in[3];
    const float* Wr  = (const float*)d_in[4];
    const void*  ei  = d_in[5];
    const void*  rel = d_in[6];
    int E = in_sizes[6];          // element count of rel == number of edges

    // 0: zero degree histogram + detect int32/int64 indices
    k_zero_detect<<<(2 * NE + 255) / 256, 256>>>((const unsigned*)ei);

    // 1: projections
    k_proj<<<(NE * 32 + 255) / 256, 256>>>(x_e, Wh, Wt, NE, 0);
    k_proj<<<(NR * 32 + 255) / 256, 256>>>(x_r, Wr, nullptr, NR, 1);

    // 2: degrees + rel cast
    k_hist<<<(E + 255) / 256, 256>>>(ei, rel, E);

    // 3: exclusive scan -> CSR offsets + cursors
    k_scan<<<1, 1024>>>(E);

    // 4: counting-sort edges into CSR
    k_fill<<<(E + 255) / 256, 256>>>(ei, E);

    // 5: per-(node,side) softmax + weighted aggregation, one store per row half
    k_agg<<<(2 * NE * 32 + 255) / 256, 256>>>(x_r, (float*)d_out);
}

// round 2
// speedup vs baseline: 1.6104x; 1.6104x over previous
#include <cuda_runtime.h>
#include <cuda_bf16.h>
#include <cstdint>

// Problem constants (fixed by the dataset)
#define NE 50000
#define NR 2000
#define EMAX 800000
#define NHEAD 8
#define DIM 128
#define NEG_SLOPE 0.01f
#define NSEG (2 * NE)
#define TILE 512
#define NTILES ((NSEG + TILE - 1) / TILE)   // 196

// ---------------- scratch (static device globals; no allocation) -------------
__device__ float g_ph[NE * NHEAD];      // x_e @ Wh.T
__device__ float g_pt[NE * NHEAD];      // x_e @ Wt.T
__device__ float g_pr[NR * NHEAD];      // x_r @ Wr.T
__device__ int   g_deg[NSEG];           // degrees: [0,NE)=h side, [NE,2NE)=t side
__device__ int   g_coffs[NSEG + 1];     // exclusive offsets (combined h|t CSR)
__device__ int   g_cur[NSEG];           // scatter cursors
__device__ int   g_elist[2 * EMAX];     // *** rel id *** per slot, grouped by (side,node)
__device__ int2  g_ht[EMAX];            // decoded (h, t) per edge
__device__ int   g_rel32[EMAX];         // rel cast to int32
__device__ int   g_tsum[NTILES];        // per-tile degree sums
__device__ int   g_toff[NTILES];        // per-tile exclusive offsets
__device__ int   g_is64;                // 1 if edge_index/rel are int64

__device__ __forceinline__ float lrelu(float s) {
    return (s > 0.0f) ? s : NEG_SLOPE * s;
}

// ---------------- kernel 0: zero degrees + detect index width ----------------
__global__ void k_zero_detect(const unsigned* ei_words) {
    int i = blockIdx.x * blockDim.x + threadIdx.x;
    if (i < NSEG) g_deg[i] = 0;
    if (blockIdx.x == 0 && threadIdx.x < 32) {
        // If int64: odd 32-bit words are the (zero) high halves of small values.
        unsigned w = ei_words[2 * threadIdx.x + 1];
        unsigned ball = __ballot_sync(0xffffffffu, w == 0u);
        if (threadIdx.x == 0) g_is64 = (ball == 0xffffffffu) ? 1 : 0;
    }
}

// ---------------- kernel 1: projections (warp per row) -----------------------
__global__ __launch_bounds__(256) void k_proj(const float* __restrict__ x,
                                              const float* __restrict__ Wa,
                                              const float* __restrict__ Wb,
                                              int n, int mode) {
    int w = (blockIdx.x * blockDim.x + threadIdx.x) >> 5;
    int lane = threadIdx.x & 31;
    if (w >= n) return;
    float* pa = (mode == 0) ? g_ph : g_pr;
    float* pb = (mode == 0) ? g_pt : nullptr;

    const float* xr = x + (long)w * DIM;
    float x0 = xr[lane], x1 = xr[lane + 32], x2 = xr[lane + 64], x3 = xr[lane + 96];

#pragma unroll
    for (int h = 0; h < NHEAD; h++) {
        const float* wa = Wa + h * DIM;
        float a = x0 * wa[lane] + x1 * wa[lane + 32] + x2 * wa[lane + 64] + x3 * wa[lane + 96];
#pragma unroll
        for (int off = 16; off > 0; off >>= 1) a += __shfl_xor_sync(0xffffffffu, a, off);
        if (lane == 0) pa[w * NHEAD + h] = a;
        if (pb) {
            const float* wb = Wb + h * DIM;
            float b = x0 * wb[lane] + x1 * wb[lane + 32] + x2 * wb[lane + 64] + x3 * wb[lane + 96];
#pragma unroll
            for (int off = 16; off > 0; off >>= 1) b += __shfl_xor_sync(0xffffffffu, b, off);
            if (lane == 0) pb[w * NHEAD + h] = b;
        }
    }
}

// ---------------- kernel 2: decode indices + degree histogram ----------------
__global__ __launch_bounds__(256) void k_hist(const void* __restrict__ ei,
                                              const void* __restrict__ rel, int E) {
    int e = blockIdx.x * blockDim.x + threadIdx.x;
    if (e >= E) return;
    int is64 = g_is64;
    int h, t, r;
    if (is64) {
        h = (int)((const long long*)ei)[e];
        t = (int)((const long long*)ei)[(long)E + e];
        r = (int)((const long long*)rel)[e];
    } else {
        h = ((const int*)ei)[e];
        t = ((const int*)ei)[(long)E + e];
        r = ((const int*)rel)[e];
    }
    g_ht[e] = make_int2(h, t);
    g_rel32[e] = r;
    atomicAdd(&g_deg[h], 1);
    atomicAdd(&g_deg[NE + t], 1);
}

// ---------------- kernels 3a/3b/3c: parallel exclusive scan ------------------
__global__ __launch_bounds__(256) void k_scan_a() {
    __shared__ int sh[256];
    int tid = threadIdx.x;
    int i0 = blockIdx.x * TILE + tid * 2;
    int v = 0;
    if (i0 < NSEG) v += g_deg[i0];
    if (i0 + 1 < NSEG) v += g_deg[i0 + 1];
    sh[tid] = v;
    __syncthreads();
    for (int off = 128; off > 0; off >>= 1) {
        if (tid < off) sh[tid] += sh[tid + off];
        __syncthreads();
    }
    if (tid == 0) g_tsum[blockIdx.x] = sh[0];
}

__global__ __launch_bounds__(256) void k_scan_b(int E) {
    __shared__ int sh[256];
    int tid = threadIdx.x;
    int v = (tid < NTILES) ? g_tsum[tid] : 0;
    sh[tid] = v;
    __syncthreads();
    for (int off = 1; off < 256; off <<= 1) {
        int t = 0;
        if (tid >= off) t = sh[tid - off];
        __syncthreads();
        sh[tid] += t;
        __syncthreads();
    }
    if (tid < NTILES) g_toff[tid] = sh[tid] - v;   // exclusive
    if (tid == 0) g_coffs[NSEG] = 2 * E;
}

__global__ __launch_bounds__(512) void k_scan_c() {
    __shared__ int sh[512];
    int tid = threadIdx.x;
    int idx = blockIdx.x * TILE + tid;
    int v = (idx < NSEG) ? g_deg[idx] : 0;
    sh[tid] = v;
    __syncthreads();
    for (int off = 1; off < 512; off <<= 1) {
        int t = 0;
        if (tid >= off) t = sh[tid - off];
        __syncthreads();
        sh[tid] += t;
        __syncthreads();
    }
    if (idx < NSEG) {
        int excl = g_toff[blockIdx.x] + sh[tid] - v;
        g_coffs[idx] = excl;
        g_cur[idx] = excl;
    }
}

// ---------------- kernel 4: counting-sort scatter (stores rel directly) ------
__global__ __launch_bounds__(256) void k_fill(int E) {
    int e = blockIdx.x * blockDim.x + threadIdx.x;
    if (e >= E) return;
    int2 ht = g_ht[e];
    int r = g_rel32[e];
    int p1 = atomicAdd(&g_cur[ht.x], 1);
    g_elist[p1] = r;
    int p2 = atomicAdd(&g_cur[NE + ht.y], 1);
    g_elist[p2] = r;
}

// ---------------- kernel 5: softmax denominators + aggregation ---------------
// One warp per (side, node). Task gw in [0, NSEG): gw<NE => h side, else t side.
__global__ __launch_bounds__(256) void k_agg(const float* __restrict__ x_r,
                                             float* __restrict__ out) {
    int gw = (blockIdx.x * blockDim.x + threadIdx.x) >> 5;
    int lane = threadIdx.x & 31;
    if (gw >= NSEG) return;
    int side = (gw >= NE) ? 1 : 0;
    int node = side ? (gw - NE) : gw;
    const float* p = side ? g_pt : g_ph;

    int start = g_coffs[gw];
    int end = g_coffs[gw + 1];

    // per-node head scores (vector broadcast loads)
    const float4* pn4 = (const float4*)(p + node * NHEAD);
    float4 pnA = pn4[0], pnB = pn4[1];
    float pn[NHEAD] = {pnA.x, pnA.y, pnA.z, pnA.w, pnB.x, pnB.y, pnB.z, pnB.w};

    // ---- phase 1: denominators per head (no max subtraction: scores ~N(0,2))
    float exs[NHEAD];
#pragma unroll
    for (int h = 0; h < NHEAD; h++) exs[h] = 0.0f;
    for (int j = start + lane; j < end; j += 32) {
        int r = g_elist[j];                       // coalesced; already the rel id
        const float4* pr4 = (const float4*)(g_pr + r * NHEAD);
        float4 prA = pr4[0], prB = pr4[1];
        exs[0] += __expf(lrelu(pn[0] + prA.x));
        exs[1] += __expf(lrelu(pn[1] + prA.y));
        exs[2] += __expf(lrelu(pn[2] + prA.z));
        exs[3] += __expf(lrelu(pn[3] + prA.w));
        exs[4] += __expf(lrelu(pn[4] + prB.x));
        exs[5] += __expf(lrelu(pn[5] + prB.y));
        exs[6] += __expf(lrelu(pn[6] + prB.z));
        exs[7] += __expf(lrelu(pn[7] + prB.w));
    }
#pragma unroll
    for (int h = 0; h < NHEAD; h++) {
        float v = exs[h];
#pragma unroll
        for (int off = 16; off > 0; off >>= 1) v += __shfl_xor_sync(0xffffffffu, v, off);
        exs[h] = v;
    }

    // this lane's head (lane&7); avoid dynamic register-array indexing
    int myh = lane & 7;
    float pn_my = 0.0f, den_my = 0.0f;
#pragma unroll
    for (int h = 0; h < NHEAD; h++) {
        pn_my = (myh == h) ? pn[h] : pn_my;
        den_my = (myh == h) ? exs[h] : den_my;
    }
    float invd_my = 1.0f / (den_my + 1e-16f);

    // ---- phase 2: serial over edges, warp cooperates; unrolled by 2 for MLP
    float4 acc = make_float4(0.0f, 0.0f, 0.0f, 0.0f);
    int j = start;
    for (; j + 1 < end; j += 2) {
        int r0 = g_elist[j];                      // uniform -> broadcast
        int r1 = g_elist[j + 1];
        float e0 = __expf(lrelu(pn_my + g_pr[r0 * NHEAD + myh])) * invd_my;
        float e1 = __expf(lrelu(pn_my + g_pr[r1 * NHEAD + myh])) * invd_my;
        e0 += __shfl_xor_sync(0xffffffffu, e0, 1);
        e1 += __shfl_xor_sync(0xffffffffu, e1, 1);
        e0 += __shfl_xor_sync(0xffffffffu, e0, 2);
        e1 += __shfl_xor_sync(0xffffffffu, e1, 2);
        e0 += __shfl_xor_sync(0xffffffffu, e0, 4);
        e1 += __shfl_xor_sync(0xffffffffu, e1, 4);
        float a0 = e0 * 0.125f;
        float a1 = e1 * 0.125f;
        float4 v0 = ((const float4*)(x_r + (long)r0 * DIM))[lane];
        float4 v1 = ((const float4*)(x_r + (long)r1 * DIM))[lane];
        acc.x += a0 * v0.x + a1 * v1.x;
        acc.y += a0 * v0.y + a1 * v1.y;
        acc.z += a0 * v0.z + a1 * v1.z;
        acc.w += a0 * v0.w + a1 * v1.w;
    }
    if (j < end) {
        int r0 = g_elist[j];
        float e0 = __expf(lrelu(pn_my + g_pr[r0 * NHEAD + myh])) * invd_my;
        e0 += __shfl_xor_sync(0xffffffffu, e0, 1);
        e0 += __shfl_xor_sync(0xffffffffu, e0, 2);
        e0 += __shfl_xor_sync(0xffffffffu, e0, 4);
        float a0 = e0 * 0.125f;
        float4 v0 = ((const float4*)(x_r + (long)r0 * DIM))[lane];
        acc.x += a0 * v0.x;
        acc.y += a0 * v0.y;
        acc.z += a0 * v0.z;
        acc.w += a0 * v0.w;
    }

    ((float4*)(out + (long)node * (2 * DIM) + side * DIM))[lane] = acc;
}

// ---------------- launch ------------------------------------------------------
extern "C" void kernel_launch(void* const* d_in, const int* in_sizes, int n_in,
                              void* d_out, int out_size) {
    const float* x_e = (const float*)d_in[0];
    const float* x_r = (const float*)d_in[1];
    const float* Wh  = (const float*)d_in[2];
    const float* Wt  = (const float*)d_in[3];
    const float* Wr  = (const float*)d_in[4];
    const void*  ei  = d_in[5];
    const void*  rel = d_in[6];
    int E = in_sizes[6];          // element count of rel == number of edges

    // 0: zero degree histogram + detect int32/int64 indices
    k_zero_detect<<<(NSEG + 255) / 256, 256>>>((const unsigned*)ei);

    // 1: projections (independent of CSR build)
    k_proj<<<(NE * 32 + 255) / 256, 256>>>(x_e, Wh, Wt, NE, 0);
    k_proj<<<(NR * 32 + 255) / 256, 256>>>(x_r, Wr, nullptr, NR, 1);

    // 2: decode + degrees
    k_hist<<<(E + 255) / 256, 256>>>(ei, rel, E);

    // 3: parallel exclusive scan -> CSR offsets + cursors
    k_scan_a<<<NTILES, 256>>>();
    k_scan_b<<<1, 256>>>(E);
    k_scan_c<<<NTILES, 512>>>();

    // 4: counting-sort rel ids into CSR slots
    k_fill<<<(E + 255) / 256, 256>>>(E);

    // 5: per-(node,side) softmax + weighted aggregation, one float4 store/lane
    k_agg<<<(NSEG * 32 + 255) / 256, 256>>>(x_r, (float*)d_out);
}